// round 16
// baseline (speedup 1.0000x reference)
#include <cuda_runtime.h>

// ---------------------------------------------------------------------------
// GCN 3-layer: (GCNConv -> BN -> ReLU) x2 -> GCNConv.  N=100k, E=1.2M, D=64.
//
// R15: - gather: 8 edges in flight per warp iteration (4 LDG.128 streams,
//        4 accumulators), 32-bit indexing.
//      - hist/fill: 8 edges/thread, phase-coalesced loads (atomic MLP=8).
//      - fill overlapped with layer-1 GEMM via stream fork inside capture.
//      - everything else as R14 (FFMA2 GEMM + dinv epilogue, fused BN stats).
// ---------------------------------------------------------------------------

#define NMAX 100000
#define EMAX 1200000
#define BN_EPS 1e-5f
#define GBLK 1480
#define SCAN_ITEMS 2048
#define GEMM_SMEM ((128 * 65 + 64 * 64) * 4)

__device__ float g_bufA[NMAX * 64];
__device__ float g_bufB[NMAX * 64];
__device__ int   g_cnt[NMAX];          // zero-init; fill re-zeroes each call
__device__ int   g_cursor[NMAX];
__device__ int   g_rowoff[NMAX + 1];
__device__ float g_dinv[NMAX];
__device__ int   g_csr[EMAX];
__device__ int   g_bagg[64];
__device__ int   g_bpref[64];
__device__ volatile int g_bflag[64];
__device__ float g_pS[GBLK * 64];
__device__ float g_pQ[GBLK * 64];
__device__ float g_bnA[64];
__device__ float g_bnB[64];
__device__ int   g_is64;

// ---- packed fp32x2 FFMA2 ----------------------------------------------------
__device__ __forceinline__ unsigned long long pack2(float lo, float hi) {
    unsigned long long r;
    asm("mov.b64 %0, {%1, %2};" : "=l"(r) : "f"(lo), "f"(hi));
    return r;
}
__device__ __forceinline__ void unpack2(unsigned long long v, float& lo, float& hi) {
    asm("mov.b64 {%0, %1}, %2;" : "=f"(lo), "=f"(hi) : "l"(v));
}
__device__ __forceinline__ unsigned long long fma2(unsigned long long a,
                                                   unsigned long long b,
                                                   unsigned long long c) {
    unsigned long long d;
    asm("fma.rn.f32x2 %0, %1, %2, %3;" : "=l"(d) : "l"(a), "l"(b), "l"(c));
    return d;
}

__device__ __forceinline__ int edge_val(const void* ei, long long idx) {
    if (g_is64) return (int)((const long long*)ei)[idx];
    return ((const int*)ei)[idx];
}

// ---- detect int64-vs-int32 edge layout + zero lookback flags ----------------
__global__ void k_detect(const unsigned int* p, int E) {
    __shared__ int any;
    if (threadIdx.x == 0) any = 0;
    if (threadIdx.x < 64) g_bflag[threadIdx.x] = 0;
    __syncthreads();
    int samples = E < 4096 ? E : 4096;
    for (int i = threadIdx.x; i < samples; i += blockDim.x)
        if (p[2 * i + 1] != 0u) any = 1;
    __syncthreads();
    if (threadIdx.x == 0) g_is64 = any ? 0 : 1;
}

// ---- histogram: 8 phase-coalesced edges/thread -------------------------------
__global__ void __launch_bounds__(256) k_hist(const void* ei, int E, int total) {
    int gid = blockIdx.x * blockDim.x + threadIdx.x;
    int d[8];
#pragma unroll
    for (int i = 0; i < 8; i++) {
        int e = gid + i * total;
        if (e < E) d[i] = edge_val(ei, (long long)E + e);
    }
#pragma unroll
    for (int i = 0; i < 8; i++) {
        int e = gid + i * total;
        if (e < E) atomicAdd(&g_cnt[d[i]], 1);
    }
}

// ---- single-kernel exclusive scan (decoupled lookback) + dinv + cursor ------
__global__ void __launch_bounds__(256) k_scan(int n, int nb) {
    __shared__ int wsum[8], woff[8];
    __shared__ int s_excl;
    int tid = threadIdx.x, b = blockIdx.x;
    int base = b * SCAN_ITEMS + tid * 8;
    int v[8];
    int tsum = 0;
#pragma unroll
    for (int i = 0; i < 8; i++) {
        v[i] = (base + i < n) ? g_cnt[base + i] : 0;
        tsum += v[i];
    }
    int lane = tid & 31, wid = tid >> 5;
    int inc = tsum;
#pragma unroll
    for (int off = 1; off < 32; off <<= 1) {
        int t = __shfl_up_sync(0xffffffffu, inc, off);
        if (lane >= off) inc += t;
    }
    if (lane == 31) wsum[wid] = inc;
    __syncthreads();
    if (tid == 0) {
        int acc = 0;
#pragma unroll
        for (int w = 0; w < 8; w++) { woff[w] = acc; acc += wsum[w]; }
        int excl = 0;
        if (b == 0) {
            *(volatile int*)&g_bpref[0] = acc;
            __threadfence();
            g_bflag[0] = 2;
        } else {
            *(volatile int*)&g_bagg[b] = acc;
            __threadfence();
            g_bflag[b] = 1;
            int p = b - 1;
            while (true) {
                int f;
                do { f = g_bflag[p]; } while (f == 0);
                __threadfence();
                if (f == 2) { excl += *(volatile int*)&g_bpref[p]; break; }
                excl += *(volatile int*)&g_bagg[p];
                p--;
            }
            *(volatile int*)&g_bpref[b] = excl + acc;
            __threadfence();
            g_bflag[b] = 2;
        }
        s_excl = excl;
        if (b == nb - 1) g_rowoff[n] = excl + acc;
    }
    __syncthreads();
    int run = s_excl + woff[wid] + (inc - tsum);
#pragma unroll
    for (int i = 0; i < 8; i++) {
        int idx = base + i;
        if (idx < n) {
            g_rowoff[idx] = run;
            g_cursor[idx] = run;
            g_dinv[idx] = rsqrtf((float)(v[i] + 1));
        }
        run += v[i];
    }
}

// ---- CSR fill: 8 phase-coalesced edges/thread; re-zeroes g_cnt --------------
__global__ void __launch_bounds__(256) k_fill(const void* ei, int E, int n,
                                              int total) {
    int gid = blockIdx.x * blockDim.x + threadIdx.x;
    int s[8], d[8];
#pragma unroll
    for (int i = 0; i < 8; i++) {
        int e = gid + i * total;
        if (e < E) {
            s[i] = edge_val(ei, e);
            d[i] = edge_val(ei, (long long)E + e);
        }
    }
#pragma unroll
    for (int i = 0; i < 8; i++) {
        int e = gid + i * total;
        if (e < E) {
            int pos = atomicAdd(&g_cursor[d[i]], 1);
            g_csr[pos] = s[i];
        }
    }
    for (int i = gid; i < n; i += total) g_cnt[i] = 0;
}

// ---- fused (BN+ReLU) + GEMM + dinv row-scale --------------------------------
__global__ void __launch_bounds__(128)
k_gemm(const float* __restrict__ X, const float* __restrict__ W,
       int use_bn, float* __restrict__ H, int n) {
    extern __shared__ float sm[];
    float (*Xs)[65] = (float(*)[65])sm;
    float* Ws = sm + 128 * 65;

    int tid = threadIdx.x;
    int rowBase = blockIdx.x * 128;

    for (int i = tid; i < 64 * 64; i += 128) Ws[i] = W[i];
    for (int i = tid; i < 128 * 64; i += 128) {
        int r = i >> 6, c = i & 63;
        int gr = rowBase + r;
        float v = 0.f;
        if (gr < n) {
            v = X[gr * 64 + c];
            if (use_bn) v = fmaxf(fmaf(v, g_bnA[c], g_bnB[c]), 0.f);
        }
        Xs[r][c] = v;
    }
    __syncthreads();

    int rgrp = tid >> 3;
    int cq = tid & 7;
    int r0 = rgrp * 8;

    unsigned long long acc[8][4];
#pragma unroll
    for (int i = 0; i < 8; i++)
#pragma unroll
        for (int j = 0; j < 4; j++) acc[i][j] = 0ULL;

#pragma unroll 4
    for (int k = 0; k < 64; k++) {
        unsigned long long xx[8];
#pragma unroll
        for (int i = 0; i < 8; i++) {
            float xv = Xs[r0 + i][k];
            xx[i] = pack2(xv, xv);
        }
        const float4* Wrow = (const float4*)(Ws + k * 64);
        float4 wa = Wrow[cq * 2 + 0];
        float4 wb = Wrow[cq * 2 + 1];
        unsigned long long wv[4] = {pack2(wa.x, wa.y), pack2(wa.z, wa.w),
                                    pack2(wb.x, wb.y), pack2(wb.z, wb.w)};
#pragma unroll
        for (int i = 0; i < 8; i++)
#pragma unroll
            for (int j = 0; j < 4; j++)
                acc[i][j] = fma2(xx[i], wv[j], acc[i][j]);
    }

#pragma unroll
    for (int i = 0; i < 8; i++) {
        int gr = rowBase + r0 + i;
        if (gr < n) {
            float dv = g_dinv[gr];
            float a0, a1, a2, a3, a4, a5, a6, a7;
            unpack2(acc[i][0], a0, a1);
            unpack2(acc[i][1], a2, a3);
            unpack2(acc[i][2], a4, a5);
            unpack2(acc[i][3], a6, a7);
            float4* dst = (float4*)(H + gr * 64 + cq * 8);
            dst[0] = make_float4(a0 * dv, a1 * dv, a2 * dv, a3 * dv);
            dst[1] = make_float4(a4 * dv, a5 * dv, a6 * dv, a7 * dv);
        }
    }
}

// ---- aggregation: one node per warp; 8 edges in flight per iteration --------
__device__ __forceinline__ float4 f4add(float4 a, float4 b) {
    return make_float4(a.x + b.x, a.y + b.y, a.z + b.z, a.w + b.w);
}

__global__ void __launch_bounds__(256)
k_gather(const float4* __restrict__ Hs, const float* __restrict__ bias,
         float4* __restrict__ out, int n, int do_stats) {
    __shared__ float sS[8][64];
    __shared__ float sQ[8][64];
    int tid = threadIdx.x;
    int lane = tid & 31;
    int warp = tid >> 5;
    int c = lane & 15;                 // channel quad
    int epick = lane >> 4;             // which edge of each pair
    int gwarp = blockIdx.x * 8 + warp;
    int nwarps = gridDim.x * 8;

    float4 S = make_float4(0.f, 0.f, 0.f, 0.f);
    float4 Q = make_float4(0.f, 0.f, 0.f, 0.f);
    float4 b4 = ((const float4*)bias)[c];

    for (int node = gwarp; node < n; node += nwarps) {
        int beg = g_rowoff[node];
        int end = g_rowoff[node + 1];
        float dn = g_dinv[node];

        float4 a0 = make_float4(0.f, 0.f, 0.f, 0.f);
        float4 a1 = make_float4(0.f, 0.f, 0.f, 0.f);
        float4 a2 = make_float4(0.f, 0.f, 0.f, 0.f);
        float4 a3 = make_float4(0.f, 0.f, 0.f, 0.f);
        int j = beg;
        for (; j + 8 <= end; j += 8) {          // 8 edges / iteration
            int s0 = g_csr[j + 0 + epick];
            int s1 = g_csr[j + 2 + epick];
            int s2 = g_csr[j + 4 + epick];
            int s3 = g_csr[j + 6 + epick];
            float4 v0 = Hs[s0 * 16 + c];
            float4 v1 = Hs[s1 * 16 + c];
            float4 v2 = Hs[s2 * 16 + c];
            float4 v3 = Hs[s3 * 16 + c];
            a0 = f4add(a0, v0);
            a1 = f4add(a1, v1);
            a2 = f4add(a2, v2);
            a3 = f4add(a3, v3);
        }
        for (; j + 2 <= end; j += 2) {          // 2 edges / iteration
            int s0 = g_csr[j + epick];
            a0 = f4add(a0, Hs[s0 * 16 + c]);
        }
        if (j < end && epick == 0) {            // odd tail: lower half only
            int s0 = g_csr[j];
            a1 = f4add(a1, Hs[s0 * 16 + c]);
        }
        float4 a = f4add(f4add(a0, a1), f4add(a2, a3));
        a.x += __shfl_xor_sync(0xffffffffu, a.x, 16);
        a.y += __shfl_xor_sync(0xffffffffu, a.y, 16);
        a.z += __shfl_xor_sync(0xffffffffu, a.z, 16);
        a.w += __shfl_xor_sync(0xffffffffu, a.w, 16);

        if (epick == 0) {
            float4 self = Hs[node * 16 + c];
            float4 t = f4add(a, self);
            float4 o = make_float4(fmaf(dn, t.x, b4.x), fmaf(dn, t.y, b4.y),
                                   fmaf(dn, t.z, b4.z), fmaf(dn, t.w, b4.w));
            out[node * 16 + c] = o;
            if (do_stats) {
                S = f4add(S, o);
                Q.x = fmaf(o.x, o.x, Q.x); Q.y = fmaf(o.y, o.y, Q.y);
                Q.z = fmaf(o.z, o.z, Q.z); Q.w = fmaf(o.w, o.w, Q.w);
            }
        }
    }

    if (do_stats) {
        if (epick == 0) {
            ((float4*)&sS[warp][c * 4])[0] = S;
            ((float4*)&sQ[warp][c * 4])[0] = Q;
        }
        __syncthreads();
        if (tid < 64) {
            float s = 0.f, q = 0.f;
#pragma unroll
            for (int h = 0; h < 8; h++) { s += sS[h][tid]; q += sQ[h][tid]; }
            g_pS[blockIdx.x * 64 + tid] = s;
            g_pQ[blockIdx.x * 64 + tid] = q;
        }
    }
}

// ---- BN finalize -------------------------------------------------------------
__global__ void __launch_bounds__(256)
k_bnfinal(const float* __restrict__ gamma, const float* __restrict__ beta, int n) {
    __shared__ float shS[8], shQ[8];
    int c = blockIdx.x;
    int tid = threadIdx.x;
    float S = 0.f, Q = 0.f;
    for (int b = tid; b < GBLK; b += 256) {
        S += g_pS[b * 64 + c];
        Q += g_pQ[b * 64 + c];
    }
#pragma unroll
    for (int off = 16; off; off >>= 1) {
        S += __shfl_down_sync(0xffffffffu, S, off);
        Q += __shfl_down_sync(0xffffffffu, Q, off);
    }
    if ((tid & 31) == 0) { shS[tid >> 5] = S; shQ[tid >> 5] = Q; }
    __syncthreads();
    if (tid == 0) {
        float s = 0.f, q = 0.f;
#pragma unroll
        for (int w = 0; w < 8; w++) { s += shS[w]; q += shQ[w]; }
        float inv_n = 1.f / (float)n;
        float mean = s * inv_n;
        float var = fmaxf(q * inv_n - mean * mean, 0.f);
        float rstd = rsqrtf(var + BN_EPS);
        float a = gamma[c] * rstd;
        g_bnA[c] = a;
        g_bnB[c] = beta[c] - mean * a;
    }
}

// ---------------------------------------------------------------------------
extern "C" void kernel_launch(void* const* d_in, const int* in_sizes, int n_in,
                              void* d_out, int out_size) {
    const float* x = (const float*)d_in[0];
    const void* ei = d_in[1];
    int n = in_sizes[0] / 64;
    int E = in_sizes[1] / 2;
    if (n > NMAX || E > EMAX) return;

    int base = 2;
    if (n_in >= 13 && in_sizes[2] == 1) base = 3;
    const float* W1  = (const float*)d_in[base + 0];
    const float* b1  = (const float*)d_in[base + 1];
    const float* ga1 = (const float*)d_in[base + 2];
    const float* be1 = (const float*)d_in[base + 3];
    const float* W2  = (const float*)d_in[base + 4];
    const float* b2  = (const float*)d_in[base + 5];
    const float* ga2 = (const float*)d_in[base + 6];
    const float* be2 = (const float*)d_in[base + 7];
    const float* W3  = (const float*)d_in[base + 8];
    const float* b3  = (const float*)d_in[base + 9];

    float *bufA = nullptr, *bufB = nullptr;
    cudaGetSymbolAddress((void**)&bufA, g_bufA);
    cudaGetSymbolAddress((void**)&bufB, g_bufB);
    cudaFuncSetAttribute(k_gemm, cudaFuncAttributeMaxDynamicSharedMemorySize,
                         GEMM_SMEM);

    // one-time host-side stream/event objects (created on the uncaptured
    // correctness call; no device memory involved)
    static cudaStream_t s2 = nullptr;
    static cudaEvent_t evFork = nullptr, evJoin = nullptr;
    static int aux_ok = -1;
    if (aux_ok < 0) {
        aux_ok = 1;
        if (cudaStreamCreateWithFlags(&s2, cudaStreamNonBlocking) != cudaSuccess)
            aux_ok = 0;
        if (aux_ok &&
            cudaEventCreateWithFlags(&evFork, cudaEventDisableTiming) != cudaSuccess)
            aux_ok = 0;
        if (aux_ok &&
            cudaEventCreateWithFlags(&evJoin, cudaEventDisableTiming) != cudaSuccess)
            aux_ok = 0;
    }

    int nb = (n + SCAN_ITEMS - 1) / SCAN_ITEMS;
    int e8blk = (E + 2047) / 2048;           // 8 edges/thread, 256 thr
    int e8total = e8blk * 256;
    int gemmblk = (n + 127) / 128;

    // --- preprocessing ---
    k_detect<<<1, 256>>>((const unsigned int*)ei, E);
    k_hist<<<e8blk, 256>>>(ei, E, e8total);
    k_scan<<<nb, 256>>>(n, nb);

    if (aux_ok) {
        // fork: k_fill on s2 concurrent with layer-1 GEMM on origin stream
        cudaEventRecord(evFork, 0);
        cudaStreamWaitEvent(s2, evFork, 0);
        k_fill<<<e8blk, 256, 0, s2>>>(ei, E, n, e8total);
        cudaEventRecord(evJoin, s2);
        k_gemm<<<gemmblk, 128, GEMM_SMEM>>>(x, W1, 0, bufA, n);
        cudaStreamWaitEvent(0, evJoin, 0);
    } else {
        k_fill<<<e8blk, 256>>>(ei, E, n, e8total);
        k_gemm<<<gemmblk, 128, GEMM_SMEM>>>(x, W1, 0, bufA, n);
    }

    // --- layer 1 (gather needs CSR + Hs) ---
    k_gather<<<GBLK, 256>>>((const float4*)bufA, b1, (float4*)bufB, n, 1);
    k_bnfinal<<<64, 256>>>(ga1, be1, n);

    // --- layer 2 ---
    k_gemm<<<gemmblk, 128, GEMM_SMEM>>>(bufB, W2, 1, bufA, n);
    k_gather<<<GBLK, 256>>>((const float4*)bufA, b2, (float4*)bufB, n, 1);
    k_bnfinal<<<64, 256>>>(ga2, be2, n);

    // --- layer 3 (final output) ---
    k_gemm<<<gemmblk, 128, GEMM_SMEM>>>(bufB, W3, 1, bufA, n);
    k_gather<<<GBLK, 256>>>((const float4*)bufA, b3, (float4*)d_out, n, 0);
}